// round 12
// baseline (speedup 1.0000x reference)
#include <cuda_runtime.h>
#include <cstdint>
#include <math.h>

#define B_  64
#define T_  512
#define N_  128
#define H_  512
#define G_  2048              // 4*H
#define BT_ (B_ * T_)         // 32768
#define NBLK 128

typedef unsigned long long ull;

#define FMA2(d, a, b, c) asm("fma.rn.f32x2 %0, %1, %2, %3;" : "=l"(d) : "l"(a), "l"(b), "l"(c))
#define PACK2(d, lo, hi) asm("mov.b64 %0, {%1, %2};" : "=l"(d) : "f"(lo), "f"(hi))
#define UNPACK2(lo, hi, v) asm("mov.b64 {%0, %1}, %2;" : "=f"(lo), "=f"(hi) : "l"(v))

#define CP_ASYNC16(dst_smem_u32, src_gmem_ptr) \
    asm volatile("cp.async.cg.shared.global [%0], [%1], 16;" :: "r"(dst_smem_u32), "l"(src_gmem_ptr) : "memory")
#define CP_COMMIT() asm volatile("cp.async.commit_group;" ::: "memory")
#define CP_WAIT(n)  asm volatile("cp.async.wait_group %0;" :: "n"(n) : "memory")

// -------- device scratch --------
__device__ float g_xg[(size_t)BT_ * G_];     // X@Wx + b, [bt][4H]
__device__ float g_hs[(size_t)BT_ * H_];     // h history [b][t][H]
__device__ float g_hT2[2][256 * 128];        // h mirror, k-pair interleaved: [kp][b][2]
__device__ float g_lpart[2048];
__device__ int   g_done[128];                // per-bg counters at [bg*32] (128B apart)

__device__ __forceinline__ float sigf(float x) {
    return __fdividef(1.0f, 1.0f + __expf(-x));
}
__device__ __forceinline__ float tanhfast(float x) {
    return __fdividef(2.0f, 1.0f + __expf(-2.0f * x)) - 1.0f;
}

// ============================================================
// Kernel A: xg = X @ Wx + b  (also resets sync counters)
// ============================================================
__global__ void __launch_bounds__(256) xg_gemm(
    const float* __restrict__ X, const float* __restrict__ Wx,
    const float* __restrict__ bias)
{
    __shared__ float Xst[64 * 68];
    __shared__ float Wsd[64 * 128];
    int tid = threadIdx.x;
    if (blockIdx.x == 0 && blockIdx.y == 0 && tid < 128) g_done[tid] = 0;

    int m0 = blockIdx.y * 64;
    int n0 = blockIdx.x * 64;
    int cx = tid & 15, ry = tid >> 4;
    int c8 = cx * 8;

    ull acc[2][4] = {};
    for (int kc = 0; kc < 128; kc += 64) {
        __syncthreads();
        #pragma unroll
        for (int i = 0; i < 16; i++) {
            int idx = tid + i * 256;
            int k = idx & 63, r = idx >> 6;
            Xst[k * 68 + r] = X[(size_t)(m0 + r) * 128 + kc + k];
        }
        #pragma unroll
        for (int i = 0; i < 32; i++) {
            int idx = tid + i * 256;
            int k = idx >> 7, rem = idx & 127;
            Wsd[k * 128 + rem] = Wx[(size_t)(kc + k) * G_ + n0 + (rem >> 1)];
        }
        __syncthreads();
        #pragma unroll 8
        for (int k = 0; k < 64; k++) {
            ulonglong2 hq  = *(const ulonglong2*)&Xst[k * 68 + ry * 4];
            ulonglong2 wq0 = *(const ulonglong2*)&Wsd[k * 128 + c8];
            ulonglong2 wq1 = *(const ulonglong2*)&Wsd[k * 128 + c8 + 4];
            FMA2(acc[0][0], hq.x, wq0.x, acc[0][0]);
            FMA2(acc[0][1], hq.x, wq0.y, acc[0][1]);
            FMA2(acc[0][2], hq.x, wq1.x, acc[0][2]);
            FMA2(acc[0][3], hq.x, wq1.y, acc[0][3]);
            FMA2(acc[1][0], hq.y, wq0.x, acc[1][0]);
            FMA2(acc[1][1], hq.y, wq0.y, acc[1][1]);
            FMA2(acc[1][2], hq.y, wq1.x, acc[1][2]);
            FMA2(acc[1][3], hq.y, wq1.y, acc[1][3]);
        }
    }
    float4 bb = *(const float4*)&bias[n0 + cx * 4];
    #pragma unroll
    for (int j = 0; j < 2; j++) {
        float lo[4], hi[4];
        #pragma unroll
        for (int cp = 0; cp < 4; cp++) UNPACK2(lo[cp], hi[cp], acc[j][cp]);
        int row0 = m0 + ry * 4 + j * 2;
        *(float4*)&g_xg[(size_t)row0 * G_ + n0 + cx * 4] =
            make_float4(lo[0] + bb.x, lo[1] + bb.y, lo[2] + bb.z, lo[3] + bb.w);
        *(float4*)&g_xg[(size_t)(row0 + 1) * G_ + n0 + cx * 4] =
            make_float4(hi[0] + bb.x, hi[1] + bb.y, hi[2] + bb.z, hi[3] + bb.w);
    }
}

// ============================================================
// Kernel B: persistent LSTM scan. k-parity f32x2 core with 8-way
// k-split and fused reduce->phase2 (no gsum stage).
// Thread GEMM coords: cg(8 cols) x bh(4 batches) x kq(8 k-slices).
//   W2  [256 kp][132] : k-parity interleaved weights (as R11)
//   h2  [256 kp][36]  : k-parity interleaved h (scr region)
//   red [8 kq][1284]  : [kq][c*20 + b] partials (scr region)
// ============================================================
#define W2_FLOATS   (256 * 132)             // 33792
#define SCR_FLOATS  (8 * 1284)              // 10272 (>= h2's 256*36=9216)
#define SMEM_SCAN   ((W2_FLOATS + SCR_FLOATS + 256) * 4)   // 177280 B

__global__ void __launch_bounds__(256, 1) lstm_scan(const float* __restrict__ Wh)
{
    extern __shared__ float smem[];
    float* W2     = smem;                        // [256][132]
    float* scr    = smem + W2_FLOATS;            // h2 / red
    float* hstage = scr + SCR_FLOATS;            // [16 u][16 b]

    int tid = threadIdx.x;
    int bid = blockIdx.x;
    int ug = bid >> 2, bg = bid & 3;
    int u0 = ug * 16;
    int* donep = &g_done[bg * 32];

    // stage W2 once: k-parity interleaved, padded rows
    for (int i = 0; i < 128; i++) {
        int idx = tid + i * 256;                  // 0..32767
        int k = idx >> 6, c = idx & 63;
        W2[(k >> 1) * 132 + c * 2 + (k & 1)] =
            Wh[(size_t)k * G_ + (c >> 4) * 512 + u0 + (c & 15)];
    }

    int cg = tid >> 5, bh = (tid >> 3) & 3, kq = tid & 7;
    int u_l = tid & 15, b_l = tid >> 4;           // phase-2 cell
    int u_cell = u0 + u_l, b_cell = bg * 16 + b_l;
    float creg = 0.0f;

    uint32_t scr_base = (uint32_t)__cvta_generic_to_shared(scr);

    __syncthreads();

    for (int t = 0; t < T_; t++) {
        // prefetch xg (hides DRAM latency behind the wait)
        float xgv[4];
        {
            size_t xoff = ((size_t)(b_cell * T_ + t)) * G_;
            #pragma unroll
            for (int g = 0; g < 4; g++)
                xgv[g] = g_xg[xoff + g * 512 + u_cell];
        }

        if (t > 0) {
            // acquire-wait on the single per-bg counter (tid0 only)
            if (tid == 0) {
                int target = 32 * t, v;
                do {
                    asm volatile("ld.acquire.gpu.global.s32 %0, [%1];"
                                 : "=r"(v) : "l"(donep));
                } while (v < target);
            }
            __syncthreads();
            const float* src = g_hT2[t & 1];
            #pragma unroll
            for (int chg = 0; chg < 4; chg++) {
                #pragma unroll
                for (int q = 0; q < 2; q++) {
                    int f = tid + q * 256;            // 0..511 16B-chunks
                    int kp = chg * 64 + (f >> 3), j = f & 7;
                    CP_ASYNC16(scr_base + (unsigned)((kp * 36 + j * 4) * 4),
                               (const void*)&src[(size_t)kp * 128 + bg * 32 + j * 4]);
                }
                CP_COMMIT();
            }
        } else {
            #pragma unroll
            for (int i = 0; i < 9; i++)               // zero h2 region
                *(float4*)&scr[(tid + i * 256) * 4] = make_float4(0.f, 0.f, 0.f, 0.f);
        }

        ull acc[8][4] = {};   // [col ci][batch bi], f32x2 over k-parity

        #pragma unroll
        for (int ch = 0; ch < 4; ch++) {
            if (t > 0) {
                switch (ch) {
                    case 0: CP_WAIT(3); break;
                    case 1: CP_WAIT(2); break;
                    case 2: CP_WAIT(1); break;
                    default: CP_WAIT(0); break;
                }
            }
            __syncthreads();
            #pragma unroll
            for (int ii = 0; ii < 8; ii++) {
                int kp = ch * 64 + ii * 8 + kq;
                const ulonglong2* wr = (const ulonglong2*)&W2[kp * 132 + cg * 16];
                ulonglong2 wa = wr[0], wb = wr[1], wc = wr[2], wd = wr[3];
                const ulonglong2* hr = (const ulonglong2*)&scr[kp * 36 + bh * 8];
                ulonglong2 ha = hr[0], hb = hr[1];
                ull w[8] = {wa.x, wa.y, wb.x, wb.y, wc.x, wc.y, wd.x, wd.y};
                ull h[4] = {ha.x, ha.y, hb.x, hb.y};
                #pragma unroll
                for (int ci = 0; ci < 8; ci++)
                    #pragma unroll
                    for (int bi = 0; bi < 4; bi++)
                        FMA2(acc[ci][bi], w[ci], h[bi], acc[ci][bi]);
            }
        }

        // ---- fold k-parity + write 8-way partials to red buffer ----
        __syncthreads();          // all h2 reads done; scr becomes red
        #pragma unroll
        for (int ci = 0; ci < 8; ci++) {
            float s[4];
            #pragma unroll
            for (int bi = 0; bi < 4; bi++) {
                float lo, hi; UNPACK2(lo, hi, acc[ci][bi]);
                s[bi] = lo + hi;
            }
            *(float4*)&scr[kq * 1284 + (cg * 8 + ci) * 20 + bh * 4] =
                make_float4(s[0], s[1], s[2], s[3]);
        }
        __syncthreads();

        // fused reduce-read + phase 2: one cell per thread
        float hval;
        {
            float sum[4];
            #pragma unroll
            for (int g = 0; g < 4; g++) {
                int cidx = (g * 16 + u_l) * 20 + b_l;
                float v = 0.0f;
                #pragma unroll
                for (int kqi = 0; kqi < 8; kqi++)
                    v += scr[kqi * 1284 + cidx];
                sum[g] = v + xgv[g];
            }
            float ig = sigf(sum[0]);
            float jg = tanhfast(sum[1]);
            float fg = sigf(sum[2] + 1.0f);                       // forget_bias = 1
            float og = sigf(sum[3]);
            creg = fg * creg + ig * jg;
            hval = og * tanhfast(creg);
            hstage[u_l * 16 + b_l] = hval;
        }
        __syncthreads();
        if (tid < 128) {       // k-pair interleaved mirror write (coalesced ull)
            int kpi = tid >> 4, bi = tid & 15;
            ull hv; PACK2(hv, hstage[(kpi * 2) * 16 + bi], hstage[(kpi * 2 + 1) * 16 + bi]);
            ((ull*)g_hT2[(t + 1) & 1])[(size_t)(ug * 8 + kpi) * 64 + bg * 16 + bi] = hv;
        }
        __threadfence();
        __syncthreads();
        if (tid == 0)
            asm volatile("red.relaxed.gpu.global.add.s32 [%0], %1;"
                         :: "l"(donep), "r"(1) : "memory");

        // history store off the inter-block critical path
        g_hs[((size_t)(b_cell * T_ + t)) * H_ + u_cell] = hval;
    }
}

// ============================================================
// Kernel C: out_loss (fast sigmoid)
// ============================================================
__global__ void __launch_bounds__(256) out_loss(
    const float* __restrict__ Wd, const float* __restrict__ bd,
    const float* __restrict__ Y)
{
    __shared__ float h_s[512 * 20];
    __shared__ float red[8];
    int tid = threadIdx.x;
    int row0 = blockIdx.x * 16;

    #pragma unroll
    for (int i = 0; i < 32; i++) {
        int idx = tid + i * 256;
        int r = idx >> 9, k = idx & 511;
        h_s[k * 20 + r] = g_hs[(size_t)(row0 + r) * H_ + k];
    }
    __syncthreads();

    int cc = tid & 127;
    int rh = tid >> 7;
    ull acc2[4] = {};
    #pragma unroll 4
    for (int k = 0; k < 512; k++) {
        float w = Wd[(size_t)k * N_ + cc];
        ull wd; PACK2(wd, w, w);
        ulonglong2 ha = *(const ulonglong2*)&h_s[k * 20 + rh * 8];
        ulonglong2 hb = *(const ulonglong2*)&h_s[k * 20 + rh * 8 + 4];
        FMA2(acc2[0], ha.x, wd, acc2[0]);
        FMA2(acc2[1], ha.y, wd, acc2[1]);
        FMA2(acc2[2], hb.x, wd, acc2[2]);
        FMA2(acc2[3], hb.y, wd, acc2[3]);
    }
    float accv[8];
    #pragma unroll
    for (int p = 0; p < 4; p++) UNPACK2(accv[2 * p], accv[2 * p + 1], acc2[p]);

    float bdc = bd[cc];
    float lsum = 0.0f;
    #pragma unroll
    for (int i = 0; i < 8; i++) {
        int row = row0 + rh * 8 + i;
        float logit = sigf(accv[i] + bdc);
        float d = Y[(size_t)row * N_ + cc] - logit;
        lsum += d * d;
    }
    #pragma unroll
    for (int o = 16; o; o >>= 1) lsum += __shfl_xor_sync(0xFFFFFFFFu, lsum, o);
    if ((tid & 31) == 0) red[tid >> 5] = lsum;
    __syncthreads();
    if (tid == 0) {
        float ssum = 0.0f;
        #pragma unroll
        for (int i = 0; i < 8; i++) ssum += red[i];
        g_lpart[blockIdx.x] = ssum;
    }
}

// ============================================================
__global__ void finalize(float* __restrict__ out)
{
    __shared__ float red[8];
    int tid = threadIdx.x;
    float sv = 0.0f;
    for (int i = tid; i < 2048; i += 256) sv += g_lpart[i];
    #pragma unroll
    for (int o = 16; o; o >>= 1) sv += __shfl_xor_sync(0xFFFFFFFFu, sv, o);
    if ((tid & 31) == 0) red[tid >> 5] = sv;
    __syncthreads();
    if (tid == 0) {
        float tt = 0.0f;
        #pragma unroll
        for (int i = 0; i < 8; i++) tt += red[i];
        out[0] = tt * (100.0f / ((float)B_ * (float)T_ * (float)N_));
    }
}

// ============================================================
extern "C" void kernel_launch(void* const* d_in, const int* in_sizes, int n_in,
                              void* d_out, int out_size)
{
    const float* X  = (const float*)d_in[0];
    const float* Y  = (const float*)d_in[1];
    const float* Wx = (const float*)d_in[2];
    const float* Wh = (const float*)d_in[3];
    const float* b  = (const float*)d_in[4];
    const float* Wd = (const float*)d_in[5];
    const float* bd = (const float*)d_in[6];
    (void)in_sizes; (void)n_in; (void)out_size;

    cudaFuncSetAttribute(lstm_scan, cudaFuncAttributeMaxDynamicSharedMemorySize, SMEM_SCAN);

    dim3 gA(G_ / 64, BT_ / 64);
    xg_gemm<<<gA, 256>>>(X, Wx, b);             // also resets g_done
    lstm_scan<<<NBLK, 256, SMEM_SCAN>>>(Wh);
    out_loss<<<BT_ / 16, 256>>>(Wd, bd, Y);
    finalize<<<1, 256>>>((float*)d_out);
}

// round 14
// speedup vs baseline: 1.3569x; 1.3569x over previous
#include <cuda_runtime.h>
#include <cstdint>
#include <math.h>

#define B_  64
#define T_  512
#define N_  128
#define H_  512
#define G_  2048              // 4*H
#define BT_ (B_ * T_)         // 32768
#define NBLK 128

typedef unsigned long long ull;

#define FMA2(d, a, b, c) asm("fma.rn.f32x2 %0, %1, %2, %3;" : "=l"(d) : "l"(a), "l"(b), "l"(c))
#define PACK2(d, lo, hi) asm("mov.b64 %0, {%1, %2};" : "=l"(d) : "f"(lo), "f"(hi))
#define UNPACK2(lo, hi, v) asm("mov.b64 {%0, %1}, %2;" : "=f"(lo), "=f"(hi) : "l"(v))

#define CP_ASYNC16(dst_smem_u32, src_gmem_ptr) \
    asm volatile("cp.async.cg.shared.global [%0], [%1], 16;" :: "r"(dst_smem_u32), "l"(src_gmem_ptr) : "memory")
#define CP_COMMIT() asm volatile("cp.async.commit_group;" ::: "memory")
#define CP_WAIT(n)  asm volatile("cp.async.wait_group %0;" :: "n"(n) : "memory")

// legacy tensor-core path (arch-agnostic PTX, works under compute_103)
#define MMA_TF32(D, A, B0, B1) \
    asm volatile("mma.sync.aligned.m16n8k8.row.col.f32.tf32.tf32.f32 " \
        "{%0,%1,%2,%3}, {%4,%5,%6,%7}, {%8,%9}, {%0,%1,%2,%3};" \
        : "+f"((D)[0]), "+f"((D)[1]), "+f"((D)[2]), "+f"((D)[3]) \
        : "r"((A)[0]), "r"((A)[1]), "r"((A)[2]), "r"((A)[3]), "r"(B0), "r"(B1))

__device__ __forceinline__ uint32_t tf32r(float x) {
    uint32_t r; asm("cvt.rna.tf32.f32 %0, %1;" : "=r"(r) : "f"(x)); return r;
}

// -------- device scratch --------
__device__ float g_xg[(size_t)BT_ * G_];     // X@Wx + b, [bt][4H]
__device__ float g_hs[(size_t)BT_ * H_];     // h history [b][t][H]
__device__ float g_hM[2][512 * 64];          // h mirror (tf32 bits), [u][b], double-buffered
__device__ float g_lpart[2048];
__device__ int   g_done[128];                // per-bg counters at [bg*32]

__device__ __forceinline__ float sigf(float x) {
    return __fdividef(1.0f, 1.0f + __expf(-x));
}
__device__ __forceinline__ float tanhfast(float x) {
    return __fdividef(2.0f, 1.0f + __expf(-2.0f * x)) - 1.0f;
}

// ============================================================
// Kernel A: xg = X @ Wx + b  (unchanged; also resets sync counters)
// ============================================================
__global__ void __launch_bounds__(256) xg_gemm(
    const float* __restrict__ X, const float* __restrict__ Wx,
    const float* __restrict__ bias)
{
    __shared__ float Xst[64 * 68];
    __shared__ float Wsd[64 * 128];
    int tid = threadIdx.x;
    if (blockIdx.x == 0 && blockIdx.y == 0 && tid < 128) g_done[tid] = 0;

    int m0 = blockIdx.y * 64;
    int n0 = blockIdx.x * 64;
    int cx = tid & 15, ry = tid >> 4;
    int c8 = cx * 8;

    ull acc[2][4] = {};
    for (int kc = 0; kc < 128; kc += 64) {
        __syncthreads();
        #pragma unroll
        for (int i = 0; i < 16; i++) {
            int idx = tid + i * 256;
            int k = idx & 63, r = idx >> 6;
            Xst[k * 68 + r] = X[(size_t)(m0 + r) * 128 + kc + k];
        }
        #pragma unroll
        for (int i = 0; i < 32; i++) {
            int idx = tid + i * 256;
            int k = idx >> 7, rem = idx & 127;
            Wsd[k * 128 + rem] = Wx[(size_t)(kc + k) * G_ + n0 + (rem >> 1)];
        }
        __syncthreads();
        #pragma unroll 8
        for (int k = 0; k < 64; k++) {
            ulonglong2 hq  = *(const ulonglong2*)&Xst[k * 68 + ry * 4];
            ulonglong2 wq0 = *(const ulonglong2*)&Wsd[k * 128 + c8];
            ulonglong2 wq1 = *(const ulonglong2*)&Wsd[k * 128 + c8 + 4];
            FMA2(acc[0][0], hq.x, wq0.x, acc[0][0]);
            FMA2(acc[0][1], hq.x, wq0.y, acc[0][1]);
            FMA2(acc[0][2], hq.x, wq1.x, acc[0][2]);
            FMA2(acc[0][3], hq.x, wq1.y, acc[0][3]);
            FMA2(acc[1][0], hq.y, wq0.x, acc[1][0]);
            FMA2(acc[1][1], hq.y, wq0.y, acc[1][1]);
            FMA2(acc[1][2], hq.y, wq1.x, acc[1][2]);
            FMA2(acc[1][3], hq.y, wq1.y, acc[1][3]);
        }
    }
    float4 bb = *(const float4*)&bias[n0 + cx * 4];
    #pragma unroll
    for (int j = 0; j < 2; j++) {
        float lo[4], hi[4];
        #pragma unroll
        for (int cp = 0; cp < 4; cp++) UNPACK2(lo[cp], hi[cp], acc[j][cp]);
        int row0 = m0 + ry * 4 + j * 2;
        *(float4*)&g_xg[(size_t)row0 * G_ + n0 + cx * 4] =
            make_float4(lo[0] + bb.x, lo[1] + bb.y, lo[2] + bb.z, lo[3] + bb.w);
        *(float4*)&g_xg[(size_t)(row0 + 1) * G_ + n0 + cx * 4] =
            make_float4(hi[0] + bb.x, hi[1] + bb.y, hi[2] + bb.z, hi[3] + bb.w);
    }
}

// ============================================================
// Kernel B: persistent LSTM scan with mma.sync tf32 (legacy HMMA).
// Block (ug, bg): D[64 gate-cols x 16 batches] = A(Wh 64x512) @ B(h 16x512)^T
// 512 threads = 16 warps = 4 m-tiles x 4 k-splits.
//   A: tf32 fragments REGISTER-RESIDENT (64 regs/thread), loaded once.
//   B: h tile streamed from g_hM via cp.async into stride-24 smem rows.
//   k-reduce over 4 splits via smem red buffer; fused phase 2 (1 cell/thread).
// ============================================================
#define BS_FLOATS  (512 * 24)               // 12288
#define RED_FLOATS (4 * 64 * 17)            // 4352
#define SMEM_SCAN  ((BS_FLOATS + RED_FLOATS + 16 * 17 + 16) * 4)   // ~67.7 KB

__global__ void __launch_bounds__(512, 1) lstm_scan(const float* __restrict__ Wh)
{
    extern __shared__ float smem[];
    float* B_s    = smem;                        // [512 k][24] (16 used + pad)
    float* red    = smem + BS_FLOATS;            // [4 ks][64 m][17]
    float* hstage = red + RED_FLOATS;            // [16 u][17]

    int tid = threadIdx.x;
    int wid = tid >> 5, lane = tid & 31;
    int bid = blockIdx.x;
    int ug = bid >> 2, bg = bid & 3;
    int u0 = ug * 16;
    int* donep = &g_done[bg * 32];

    int mt = wid & 3, ks = wid >> 2;             // m-tile, k-split
    int grp = lane >> 2, qid = lane & 3;

    // ---- preload A (Wh) tf32 fragments: 16 k-steps x 4 regs, once ----
    uint32_t a[16][4];
    #pragma unroll
    for (int kk = 0; kk < 16; kk++)
        #pragma unroll
        for (int r = 0; r < 4; r++) {
            int m_loc = grp + (r & 1) * 8;
            int k = ks * 128 + kk * 8 + qid + (r >> 1) * 4;
            a[kk][r] = tf32r(Wh[(size_t)k * G_ + mt * 512 + u0 + m_loc]);
        }

    // phase-2 cell (first 256 threads)
    int u_l = tid & 15, b_l = tid >> 4;
    int u_cell = u0 + u_l, b_cell = bg * 16 + b_l;
    float creg = 0.0f;

    uint32_t bs_base = (uint32_t)__cvta_generic_to_shared(B_s);
    const uint32_t* Bu = (const uint32_t*)B_s;

    __syncthreads();

    for (int t = 0; t < T_; t++) {
        // prefetch xg (hidden behind the wait), cells only
        float xgv[4] = {0.f, 0.f, 0.f, 0.f};
        if (tid < 256) {
            size_t xoff = ((size_t)(b_cell * T_ + t)) * G_;
            #pragma unroll
            for (int g = 0; g < 4; g++)
                xgv[g] = g_xg[xoff + g * 512 + u_cell];
        }

        if (t > 0) {
            if (tid == 0) {
                int target = 32 * t, v;
                do {
                    asm volatile("ld.acquire.gpu.global.s32 %0, [%1];"
                                 : "=r"(v) : "l"(donep));
                } while (v < target);
            }
            __syncthreads();
            const float* src = g_hM[t & 1];
            #pragma unroll
            for (int q = 0; q < 4; q++) {
                int f = tid + q * 512;               // 0..2047 16B-chunks
                int u = f >> 2, j = f & 3;
                CP_ASYNC16(bs_base + (unsigned)((u * 24 + j * 4) * 4),
                           (const void*)&src[(size_t)u * 64 + bg * 16 + j * 4]);
            }
            CP_COMMIT();
            CP_WAIT(0);
        } else {
            #pragma unroll
            for (int i = 0; i < 6; i++)
                *(float4*)&B_s[(tid + i * 512) * 4] = make_float4(0.f, 0.f, 0.f, 0.f);
        }
        __syncthreads();

        // ---- tensor-core GEMM: 16 k-steps x 2 n-tiles ----
        float d0[4] = {0.f, 0.f, 0.f, 0.f};
        float d1[4] = {0.f, 0.f, 0.f, 0.f};
        #pragma unroll
        for (int kk = 0; kk < 16; kk++) {
            int kb = ks * 128 + kk * 8;
            uint32_t b0a = Bu[(kb + qid) * 24 + grp];
            uint32_t b1a = Bu[(kb + qid + 4) * 24 + grp];
            uint32_t b0b = Bu[(kb + qid) * 24 + 8 + grp];
            uint32_t b1b = Bu[(kb + qid + 4) * 24 + 8 + grp];
            MMA_TF32(d0, a[kk], b0a, b1a);
            MMA_TF32(d1, a[kk], b0b, b1b);
        }

        // ---- write k-split partials to red ----
        {
            float* rp = red + ks * 1088 + (mt * 16) * 17;
            int nc = qid * 2;
            rp[grp * 17 + nc]           = d0[0];
            rp[grp * 17 + nc + 1]       = d0[1];
            rp[(grp + 8) * 17 + nc]     = d0[2];
            rp[(grp + 8) * 17 + nc + 1] = d0[3];
            rp[grp * 17 + 8 + nc]           = d1[0];
            rp[grp * 17 + 8 + nc + 1]       = d1[1];
            rp[(grp + 8) * 17 + 8 + nc]     = d1[2];
            rp[(grp + 8) * 17 + 8 + nc + 1] = d1[3];
        }
        __syncthreads();

        // ---- fused reduce + phase 2 (first 256 threads) ----
        if (tid < 256) {
            float sum[4];
            #pragma unroll
            for (int g = 0; g < 4; g++) {
                int cidx = (g * 16 + u_l) * 17 + b_l;
                sum[g] = red[cidx] + red[1088 + cidx] + red[2176 + cidx]
                       + red[3264 + cidx] + xgv[g];
            }
            float ig = sigf(sum[0]);
            float jg = tanhfast(sum[1]);
            float fg = sigf(sum[2] + 1.0f);                   // forget_bias = 1
            float og = sigf(sum[3]);
            creg = fg * creg + ig * jg;
            float hval = og * tanhfast(creg);
            hstage[u_l * 17 + b_l] = hval;
        }
        __syncthreads();

        // ---- publish mirror (tf32-rounded, coalesced) ----
        if (tid < 256) {
            int u_loc = tid >> 4, b_loc = tid & 15;
            float v = hstage[u_loc * 17 + b_loc];
            ((uint32_t*)g_hM[(t + 1) & 1])[(size_t)(u0 + u_loc) * 64 + bg * 16 + b_loc] = tf32r(v);
        }
        __threadfence();
        __syncthreads();
        if (tid == 0)
            asm volatile("red.relaxed.gpu.global.add.s32 [%0], %1;"
                         :: "l"(donep), "r"(1) : "memory");

        // history store (full fp32), off the inter-block critical path
        if (tid < 256)
            g_hs[((size_t)(b_cell * T_ + t)) * H_ + u_cell] = hstage[u_l * 17 + b_l];
    }
}

// ============================================================
// Kernel C: out_loss (fast sigmoid)
// ============================================================
__global__ void __launch_bounds__(256) out_loss(
    const float* __restrict__ Wd, const float* __restrict__ bd,
    const float* __restrict__ Y)
{
    __shared__ float h_s[512 * 20];
    __shared__ float red[8];
    int tid = threadIdx.x;
    int row0 = blockIdx.x * 16;

    #pragma unroll
    for (int i = 0; i < 32; i++) {
        int idx = tid + i * 256;
        int r = idx >> 9, k = idx & 511;
        h_s[k * 20 + r] = g_hs[(size_t)(row0 + r) * H_ + k];
    }
    __syncthreads();

    int cc = tid & 127;
    int rh = tid >> 7;
    ull acc2[4] = {};
    #pragma unroll 4
    for (int k = 0; k < 512; k++) {
        float w = Wd[(size_t)k * N_ + cc];
        ull wd; PACK2(wd, w, w);
        ulonglong2 ha = *(const ulonglong2*)&h_s[k * 20 + rh * 8];
        ulonglong2 hb = *(const ulonglong2*)&h_s[k * 20 + rh * 8 + 4];
        FMA2(acc2[0], ha.x, wd, acc2[0]);
        FMA2(acc2[1], ha.y, wd, acc2[1]);
        FMA2(acc2[2], hb.x, wd, acc2[2]);
        FMA2(acc2[3], hb.y, wd, acc2[3]);
    }
    float accv[8];
    #pragma unroll
    for (int p = 0; p < 4; p++) UNPACK2(accv[2 * p], accv[2 * p + 1], acc2[p]);

    float bdc = bd[cc];
    float lsum = 0.0f;
    #pragma unroll
    for (int i = 0; i < 8; i++) {
        int row = row0 + rh * 8 + i;
        float logit = sigf(accv[i] + bdc);
        float d = Y[(size_t)row * N_ + cc] - logit;
        lsum += d * d;
    }
    #pragma unroll
    for (int o = 16; o; o >>= 1) lsum += __shfl_xor_sync(0xFFFFFFFFu, lsum, o);
    if ((tid & 31) == 0) red[tid >> 5] = lsum;
    __syncthreads();
    if (tid == 0) {
        float ssum = 0.0f;
        #pragma unroll
        for (int i = 0; i < 8; i++) ssum += red[i];
        g_lpart[blockIdx.x] = ssum;
    }
}

// ============================================================
__global__ void finalize(float* __restrict__ out)
{
    __shared__ float red[8];
    int tid = threadIdx.x;
    float sv = 0.0f;
    for (int i = tid; i < 2048; i += 256) sv += g_lpart[i];
    #pragma unroll
    for (int o = 16; o; o >>= 1) sv += __shfl_xor_sync(0xFFFFFFFFu, sv, o);
    if ((tid & 31) == 0) red[tid >> 5] = sv;
    __syncthreads();
    if (tid == 0) {
        float tt = 0.0f;
        #pragma unroll
        for (int i = 0; i < 8; i++) tt += red[i];
        out[0] = tt * (100.0f / ((float)B_ * (float)T_ * (float)N_));
    }
}

// ============================================================
extern "C" void kernel_launch(void* const* d_in, const int* in_sizes, int n_in,
                              void* d_out, int out_size)
{
    const float* X  = (const float*)d_in[0];
    const float* Y  = (const float*)d_in[1];
    const float* Wx = (const float*)d_in[2];
    const float* Wh = (const float*)d_in[3];
    const float* b  = (const float*)d_in[4];
    const float* Wd = (const float*)d_in[5];
    const float* bd = (const float*)d_in[6];
    (void)in_sizes; (void)n_in; (void)out_size;

    cudaFuncSetAttribute(lstm_scan, cudaFuncAttributeMaxDynamicSharedMemorySize, SMEM_SCAN);

    dim3 gA(G_ / 64, BT_ / 64);
    xg_gemm<<<gA, 256>>>(X, Wx, b);             // also resets g_done
    lstm_scan<<<NBLK, 512, SMEM_SCAN>>>(Wh);
    out_loss<<<BT_ / 16, 256>>>(Wd, bd, Y);
    finalize<<<1, 256>>>((float*)d_out);
}

// round 15
// speedup vs baseline: 1.8681x; 1.3768x over previous
#include <cuda_runtime.h>
#include <cstdint>
#include <math.h>

#define B_  64
#define T_  512
#define N_  128
#define H_  512
#define G_  2048              // 4*H
#define BT_ (B_ * T_)         // 32768
#define NBLK 128

typedef unsigned long long ull;

#define FMA2(d, a, b, c) asm("fma.rn.f32x2 %0, %1, %2, %3;" : "=l"(d) : "l"(a), "l"(b), "l"(c))
#define PACK2(d, lo, hi) asm("mov.b64 %0, {%1, %2};" : "=l"(d) : "f"(lo), "f"(hi))
#define UNPACK2(lo, hi, v) asm("mov.b64 {%0, %1}, %2;" : "=f"(lo), "=f"(hi) : "l"(v))

#define CP_ASYNC16(dst_smem_u32, src_gmem_ptr) \
    asm volatile("cp.async.cg.shared.global [%0], [%1], 16;" :: "r"(dst_smem_u32), "l"(src_gmem_ptr) : "memory")
#define CP_COMMIT() asm volatile("cp.async.commit_group;" ::: "memory")
#define CP_WAIT(n)  asm volatile("cp.async.wait_group %0;" :: "n"(n) : "memory")

// legacy tensor-core path (arch-agnostic PTX, works under compute_103)
#define MMA_TF32(D, A, B0, B1) \
    asm volatile("mma.sync.aligned.m16n8k8.row.col.f32.tf32.tf32.f32 " \
        "{%0,%1,%2,%3}, {%4,%5,%6,%7}, {%8,%9}, {%0,%1,%2,%3};" \
        : "+f"((D)[0]), "+f"((D)[1]), "+f"((D)[2]), "+f"((D)[3]) \
        : "r"((A)[0]), "r"((A)[1]), "r"((A)[2]), "r"((A)[3]), "r"(B0), "r"(B1))

__device__ __forceinline__ uint32_t tf32r(float x) {
    uint32_t r; asm("cvt.rna.tf32.f32 %0, %1;" : "=r"(r) : "f"(x)); return r;
}

// -------- device scratch --------
__device__ float g_xg[(size_t)BT_ * G_];     // X@Wx + b, [bt][4H]
__device__ float g_hs[(size_t)BT_ * H_];     // h history [b][t][H]
__device__ float g_hM[2][512 * 64];          // h mirror (tf32 bits), [u][b], double-buffered
__device__ float g_lpart[2048];
__device__ int   g_done[128];                // per-bg counters at [bg*32]

__device__ __forceinline__ float sigf(float x) {
    return __fdividef(1.0f, 1.0f + __expf(-x));
}
__device__ __forceinline__ float tanhfast(float x) {
    return __fdividef(2.0f, 1.0f + __expf(-2.0f * x)) - 1.0f;
}

// ============================================================
// Kernel A: xg = X @ Wx + b via mma.sync tf32.
// Block = 64 rows x 64 cols, K=128 in one smem residency.
// 8 warps = 4 m-tiles x 2 n-quads (4 n-tiles each).
// ============================================================
#define XG_SMEM ((64 * 132 + 128 * 68) * 4)   // Xs + Ws tf32, 68608 B

__global__ void __launch_bounds__(256) xg_gemm(
    const float* __restrict__ X, const float* __restrict__ Wx,
    const float* __restrict__ bias)
{
    extern __shared__ uint32_t smemu[];
    uint32_t* Xs = smemu;                 // [64 m][132] tf32 (pad 132)
    uint32_t* Ws = smemu + 64 * 132;      // [128 k][68] tf32 (pad 68)

    int tid = threadIdx.x;
    if (blockIdx.x == 0 && blockIdx.y == 0 && tid < 128) g_done[tid] = 0;

    int m0 = blockIdx.y * 64;
    int n0 = blockIdx.x * 64;

    // stage X tile (64x128) and W tile (128x64) as tf32
    #pragma unroll
    for (int i = 0; i < 32; i++) {
        int idx = tid + i * 256;              // 0..8191
        int m = idx >> 7, k = idx & 127;
        Xs[m * 132 + k] = tf32r(X[(size_t)(m0 + m) * 128 + k]);
    }
    #pragma unroll
    for (int i = 0; i < 32; i++) {
        int idx = tid + i * 256;
        int k = idx >> 6, n = idx & 63;
        Ws[k * 68 + n] = tf32r(Wx[(size_t)k * G_ + n0 + n]);
    }
    __syncthreads();

    int wid = tid >> 5, lane = tid & 31;
    int mt = wid & 3, nq = wid >> 2;          // m-tile 0..3, n-quad 0..1
    int grp = lane >> 2, qid = lane & 3;

    float d[4][4] = {};                       // [n-tile j][frag]
    #pragma unroll
    for (int kk = 0; kk < 16; kk++) {
        int kb = kk * 8;
        uint32_t a[4];
        a[0] = Xs[(mt * 16 + grp) * 132 + kb + qid];
        a[1] = Xs[(mt * 16 + grp + 8) * 132 + kb + qid];
        a[2] = Xs[(mt * 16 + grp) * 132 + kb + qid + 4];
        a[3] = Xs[(mt * 16 + grp + 8) * 132 + kb + qid + 4];
        #pragma unroll
        for (int j = 0; j < 4; j++) {
            int nt = nq * 4 + j;
            uint32_t b0 = Ws[(kb + qid) * 68 + nt * 8 + grp];
            uint32_t b1 = Ws[(kb + qid + 4) * 68 + nt * 8 + grp];
            MMA_TF32(d[j], a, b0, b1);
        }
    }

    // store D + bias (float2 runs; gn even since nc = qid*2)
    #pragma unroll
    for (int j = 0; j < 4; j++) {
        int gn = n0 + (nq * 4 + j) * 8 + qid * 2;
        float2 bb = *(const float2*)&bias[gn];
        int row0 = m0 + mt * 16 + grp;
        *(float2*)&g_xg[(size_t)row0 * G_ + gn] =
            make_float2(d[j][0] + bb.x, d[j][1] + bb.y);
        *(float2*)&g_xg[(size_t)(row0 + 8) * G_ + gn] =
            make_float2(d[j][2] + bb.x, d[j][3] + bb.y);
    }
}

// ============================================================
// Kernel B: persistent LSTM scan with mma.sync tf32 (unchanged from R14).
// ============================================================
#define BS_FLOATS  (512 * 24)               // 12288
#define RED_FLOATS (4 * 64 * 17)            // 4352
#define SMEM_SCAN  ((BS_FLOATS + RED_FLOATS + 16 * 17 + 16) * 4)

__global__ void __launch_bounds__(512, 1) lstm_scan(const float* __restrict__ Wh)
{
    extern __shared__ float smem[];
    float* B_s    = smem;                        // [512 k][24]
    float* red    = smem + BS_FLOATS;            // [4 ks][64 m][17]
    float* hstage = red + RED_FLOATS;            // [16 u][17]

    int tid = threadIdx.x;
    int wid = tid >> 5, lane = tid & 31;
    int bid = blockIdx.x;
    int ug = bid >> 2, bg = bid & 3;
    int u0 = ug * 16;
    int* donep = &g_done[bg * 32];

    int mt = wid & 3, ks = wid >> 2;             // m-tile, k-split
    int grp = lane >> 2, qid = lane & 3;

    // preload A (Wh) tf32 fragments, once
    uint32_t a[16][4];
    #pragma unroll
    for (int kk = 0; kk < 16; kk++)
        #pragma unroll
        for (int r = 0; r < 4; r++) {
            int m_loc = grp + (r & 1) * 8;
            int k = ks * 128 + kk * 8 + qid + (r >> 1) * 4;
            a[kk][r] = tf32r(Wh[(size_t)k * G_ + mt * 512 + u0 + m_loc]);
        }

    int u_l = tid & 15, b_l = tid >> 4;
    int u_cell = u0 + u_l, b_cell = bg * 16 + b_l;
    float creg = 0.0f;

    uint32_t bs_base = (uint32_t)__cvta_generic_to_shared(B_s);
    const uint32_t* Bu = (const uint32_t*)B_s;

    __syncthreads();

    for (int t = 0; t < T_; t++) {
        float xgv[4] = {0.f, 0.f, 0.f, 0.f};
        if (tid < 256) {
            size_t xoff = ((size_t)(b_cell * T_ + t)) * G_;
            #pragma unroll
            for (int g = 0; g < 4; g++)
                xgv[g] = g_xg[xoff + g * 512 + u_cell];
        }

        if (t > 0) {
            if (tid == 0) {
                int target = 32 * t, v;
                do {
                    asm volatile("ld.acquire.gpu.global.s32 %0, [%1];"
                                 : "=r"(v) : "l"(donep));
                } while (v < target);
            }
            __syncthreads();
            const float* src = g_hM[t & 1];
            #pragma unroll
            for (int q = 0; q < 4; q++) {
                int f = tid + q * 512;               // 0..2047 16B-chunks
                int u = f >> 2, j = f & 3;
                CP_ASYNC16(bs_base + (unsigned)((u * 24 + j * 4) * 4),
                           (const void*)&src[(size_t)u * 64 + bg * 16 + j * 4]);
            }
            CP_COMMIT();
            CP_WAIT(0);
        } else {
            #pragma unroll
            for (int i = 0; i < 6; i++)
                *(float4*)&B_s[(tid + i * 512) * 4] = make_float4(0.f, 0.f, 0.f, 0.f);
        }
        __syncthreads();

        float d0[4] = {0.f, 0.f, 0.f, 0.f};
        float d1[4] = {0.f, 0.f, 0.f, 0.f};
        #pragma unroll
        for (int kk = 0; kk < 16; kk++) {
            int kb = ks * 128 + kk * 8;
            uint32_t b0a = Bu[(kb + qid) * 24 + grp];
            uint32_t b1a = Bu[(kb + qid + 4) * 24 + grp];
            uint32_t b0b = Bu[(kb + qid) * 24 + 8 + grp];
            uint32_t b1b = Bu[(kb + qid + 4) * 24 + 8 + grp];
            MMA_TF32(d0, a[kk], b0a, b1a);
            MMA_TF32(d1, a[kk], b0b, b1b);
        }

        {
            float* rp = red + ks * 1088 + (mt * 16) * 17;
            int nc = qid * 2;
            rp[grp * 17 + nc]           = d0[0];
            rp[grp * 17 + nc + 1]       = d0[1];
            rp[(grp + 8) * 17 + nc]     = d0[2];
            rp[(grp + 8) * 17 + nc + 1] = d0[3];
            rp[grp * 17 + 8 + nc]           = d1[0];
            rp[grp * 17 + 8 + nc + 1]       = d1[1];
            rp[(grp + 8) * 17 + 8 + nc]     = d1[2];
            rp[(grp + 8) * 17 + 8 + nc + 1] = d1[3];
        }
        __syncthreads();

        if (tid < 256) {
            float sum[4];
            #pragma unroll
            for (int g = 0; g < 4; g++) {
                int cidx = (g * 16 + u_l) * 17 + b_l;
                sum[g] = red[cidx] + red[1088 + cidx] + red[2176 + cidx]
                       + red[3264 + cidx] + xgv[g];
            }
            float ig = sigf(sum[0]);
            float jg = tanhfast(sum[1]);
            float fg = sigf(sum[2] + 1.0f);                   // forget_bias = 1
            float og = sigf(sum[3]);
            creg = fg * creg + ig * jg;
            float hval = og * tanhfast(creg);
            hstage[u_l * 17 + b_l] = hval;
        }
        __syncthreads();

        if (tid < 256) {
            int u_loc = tid >> 4, b_loc = tid & 15;
            float v = hstage[u_loc * 17 + b_loc];
            ((uint32_t*)g_hM[(t + 1) & 1])[(size_t)(u0 + u_loc) * 64 + bg * 16 + b_loc] = tf32r(v);
        }
        __threadfence();
        __syncthreads();
        if (tid == 0)
            asm volatile("red.relaxed.gpu.global.add.s32 [%0], %1;"
                         :: "l"(donep), "r"(1) : "memory");

        if (tid < 256)
            g_hs[((size_t)(b_cell * T_ + t)) * H_ + u_cell] = hstage[u_l * 17 + b_l];
    }
}

// ============================================================
// Kernel C: out_loss (unchanged)
// ============================================================
__global__ void __launch_bounds__(256) out_loss(
    const float* __restrict__ Wd, const float* __restrict__ bd,
    const float* __restrict__ Y)
{
    __shared__ float h_s[512 * 20];
    __shared__ float red[8];
    int tid = threadIdx.x;
    int row0 = blockIdx.x * 16;

    #pragma unroll
    for (int i = 0; i < 32; i++) {
        int idx = tid + i * 256;
        int r = idx >> 9, k = idx & 511;
        h_s[k * 20 + r] = g_hs[(size_t)(row0 + r) * H_ + k];
    }
    __syncthreads();

    int cc = tid & 127;
    int rh = tid >> 7;
    ull acc2[4] = {};
    #pragma unroll 4
    for (int k = 0; k < 512; k++) {
        float w = Wd[(size_t)k * N_ + cc];
        ull wd; PACK2(wd, w, w);
        ulonglong2 ha = *(const ulonglong2*)&h_s[k * 20 + rh * 8];
        ulonglong2 hb = *(const ulonglong2*)&h_s[k * 20 + rh * 8 + 4];
        FMA2(acc2[0], ha.x, wd, acc2[0]);
        FMA2(acc2[1], ha.y, wd, acc2[1]);
        FMA2(acc2[2], hb.x, wd, acc2[2]);
        FMA2(acc2[3], hb.y, wd, acc2[3]);
    }
    float accv[8];
    #pragma unroll
    for (int p = 0; p < 4; p++) UNPACK2(accv[2 * p], accv[2 * p + 1], acc2[p]);

    float bdc = bd[cc];
    float lsum = 0.0f;
    #pragma unroll
    for (int i = 0; i < 8; i++) {
        int row = row0 + rh * 8 + i;
        float logit = sigf(accv[i] + bdc);
        float d = Y[(size_t)row * N_ + cc] - logit;
        lsum += d * d;
    }
    #pragma unroll
    for (int o = 16; o; o >>= 1) lsum += __shfl_xor_sync(0xFFFFFFFFu, lsum, o);
    if ((tid & 31) == 0) red[tid >> 5] = lsum;
    __syncthreads();
    if (tid == 0) {
        float ssum = 0.0f;
        #pragma unroll
        for (int i = 0; i < 8; i++) ssum += red[i];
        g_lpart[blockIdx.x] = ssum;
    }
}

// ============================================================
__global__ void finalize(float* __restrict__ out)
{
    __shared__ float red[8];
    int tid = threadIdx.x;
    float sv = 0.0f;
    for (int i = tid; i < 2048; i += 256) sv += g_lpart[i];
    #pragma unroll
    for (int o = 16; o; o >>= 1) sv += __shfl_xor_sync(0xFFFFFFFFu, sv, o);
    if ((tid & 31) == 0) red[tid >> 5] = sv;
    __syncthreads();
    if (tid == 0) {
        float tt = 0.0f;
        #pragma unroll
        for (int i = 0; i < 8; i++) tt += red[i];
        out[0] = tt * (100.0f / ((float)B_ * (float)T_ * (float)N_));
    }
}

// ============================================================
extern "C" void kernel_launch(void* const* d_in, const int* in_sizes, int n_in,
                              void* d_out, int out_size)
{
    const float* X  = (const float*)d_in[0];
    const float* Y  = (const float*)d_in[1];
    const float* Wx = (const float*)d_in[2];
    const float* Wh = (const float*)d_in[3];
    const float* b  = (const float*)d_in[4];
    const float* Wd = (const float*)d_in[5];
    const float* bd = (const float*)d_in[6];
    (void)in_sizes; (void)n_in; (void)out_size;

    cudaFuncSetAttribute(xg_gemm, cudaFuncAttributeMaxDynamicSharedMemorySize, XG_SMEM);
    cudaFuncSetAttribute(lstm_scan, cudaFuncAttributeMaxDynamicSharedMemorySize, SMEM_SCAN);

    dim3 gA(G_ / 64, BT_ / 64);                 // 32 x 512
    xg_gemm<<<gA, 256, XG_SMEM>>>(X, Wx, b);    // also resets g_done
    lstm_scan<<<NBLK, 512, SMEM_SCAN>>>(Wh);
    out_loss<<<BT_ / 16, 256>>>(Wd, bd, Y);
    finalize<<<1, 256>>>((float*)d_out);
}

// round 16
// speedup vs baseline: 1.9423x; 1.0397x over previous
#include <cuda_runtime.h>
#include <cstdint>
#include <math.h>

#define B_  64
#define T_  512
#define N_  128
#define H_  512
#define G_  2048              // 4*H
#define BT_ (B_ * T_)         // 32768
#define NBLK 128
#define NLOSS 1024            // out_loss partials

typedef unsigned long long ull;

#define FMA2(d, a, b, c) asm("fma.rn.f32x2 %0, %1, %2, %3;" : "=l"(d) : "l"(a), "l"(b), "l"(c))
#define PACK2(d, lo, hi) asm("mov.b64 %0, {%1, %2};" : "=l"(d) : "f"(lo), "f"(hi))
#define UNPACK2(lo, hi, v) asm("mov.b64 {%0, %1}, %2;" : "=f"(lo), "=f"(hi) : "l"(v))

#define CP_ASYNC16(dst_smem_u32, src_gmem_ptr) \
    asm volatile("cp.async.cg.shared.global [%0], [%1], 16;" :: "r"(dst_smem_u32), "l"(src_gmem_ptr) : "memory")
#define CP_COMMIT() asm volatile("cp.async.commit_group;" ::: "memory")
#define CP_WAIT(n)  asm volatile("cp.async.wait_group %0;" :: "n"(n) : "memory")

// legacy tensor-core path (arch-agnostic PTX, works under compute_103)
#define MMA_TF32(D, A, B0, B1) \
    asm volatile("mma.sync.aligned.m16n8k8.row.col.f32.tf32.tf32.f32 " \
        "{%0,%1,%2,%3}, {%4,%5,%6,%7}, {%8,%9}, {%0,%1,%2,%3};" \
        : "+f"((D)[0]), "+f"((D)[1]), "+f"((D)[2]), "+f"((D)[3]) \
        : "r"((A)[0]), "r"((A)[1]), "r"((A)[2]), "r"((A)[3]), "r"(B0), "r"(B1))

__device__ __forceinline__ uint32_t tf32r(float x) {
    uint32_t r; asm("cvt.rna.tf32.f32 %0, %1;" : "=r"(r) : "f"(x)); return r;
}

// -------- device scratch --------
__device__ float g_xg[(size_t)BT_ * G_];     // X@Wx + b, [bt][4H]
__device__ float g_hs[(size_t)BT_ * H_];     // h history [b][t][H]
__device__ float g_hM[2][512 * 64];          // h mirror (tf32 bits), [u][b], double-buffered
__device__ float g_lpart[NLOSS];
__device__ int   g_done[128];                // per-bg counters at [bg*32]

__device__ __forceinline__ float sigf(float x) {
    return __fdividef(1.0f, 1.0f + __expf(-x));
}
__device__ __forceinline__ float tanhfast(float x) {
    return __fdividef(2.0f, 1.0f + __expf(-2.0f * x)) - 1.0f;
}

// ============================================================
// Kernel A: xg = X @ Wx + b via mma.sync tf32 (unchanged from R15).
// ============================================================
#define XG_SMEM ((64 * 132 + 128 * 68) * 4)   // 68608 B

__global__ void __launch_bounds__(256) xg_gemm(
    const float* __restrict__ X, const float* __restrict__ Wx,
    const float* __restrict__ bias)
{
    extern __shared__ uint32_t smemu[];
    uint32_t* Xs = smemu;                 // [64 m][132] tf32
    uint32_t* Ws = smemu + 64 * 132;      // [128 k][68] tf32

    int tid = threadIdx.x;
    if (blockIdx.x == 0 && blockIdx.y == 0 && tid < 128) g_done[tid] = 0;

    int m0 = blockIdx.y * 64;
    int n0 = blockIdx.x * 64;

    #pragma unroll
    for (int i = 0; i < 32; i++) {
        int idx = tid + i * 256;              // 0..8191
        int m = idx >> 7, k = idx & 127;
        Xs[m * 132 + k] = tf32r(X[(size_t)(m0 + m) * 128 + k]);
    }
    #pragma unroll
    for (int i = 0; i < 32; i++) {
        int idx = tid + i * 256;
        int k = idx >> 6, n = idx & 63;
        Ws[k * 68 + n] = tf32r(Wx[(size_t)k * G_ + n0 + n]);
    }
    __syncthreads();

    int wid = tid >> 5, lane = tid & 31;
    int mt = wid & 3, nq = wid >> 2;
    int grp = lane >> 2, qid = lane & 3;

    float d[4][4] = {};
    #pragma unroll
    for (int kk = 0; kk < 16; kk++) {
        int kb = kk * 8;
        uint32_t a[4];
        a[0] = Xs[(mt * 16 + grp) * 132 + kb + qid];
        a[1] = Xs[(mt * 16 + grp + 8) * 132 + kb + qid];
        a[2] = Xs[(mt * 16 + grp) * 132 + kb + qid + 4];
        a[3] = Xs[(mt * 16 + grp + 8) * 132 + kb + qid + 4];
        #pragma unroll
        for (int j = 0; j < 4; j++) {
            int nt = nq * 4 + j;
            uint32_t b0 = Ws[(kb + qid) * 68 + nt * 8 + grp];
            uint32_t b1 = Ws[(kb + qid + 4) * 68 + nt * 8 + grp];
            MMA_TF32(d[j], a, b0, b1);
        }
    }

    #pragma unroll
    for (int j = 0; j < 4; j++) {
        int gn = n0 + (nq * 4 + j) * 8 + qid * 2;
        float2 bb = *(const float2*)&bias[gn];
        int row0 = m0 + mt * 16 + grp;
        *(float2*)&g_xg[(size_t)row0 * G_ + gn] =
            make_float2(d[j][0] + bb.x, d[j][1] + bb.y);
        *(float2*)&g_xg[(size_t)(row0 + 8) * G_ + gn] =
            make_float2(d[j][2] + bb.x, d[j][3] + bb.y);
    }
}

// ============================================================
// Kernel B: persistent LSTM scan with mma.sync tf32 (unchanged from R14/15).
// ============================================================
#define BS_FLOATS  (512 * 24)
#define RED_FLOATS (4 * 64 * 17)
#define SMEM_SCAN  ((BS_FLOATS + RED_FLOATS + 16 * 17 + 16) * 4)

__global__ void __launch_bounds__(512, 1) lstm_scan(const float* __restrict__ Wh)
{
    extern __shared__ float smem[];
    float* B_s    = smem;                        // [512 k][24]
    float* red    = smem + BS_FLOATS;            // [4 ks][64 m][17]
    float* hstage = red + RED_FLOATS;            // [16 u][17]

    int tid = threadIdx.x;
    int wid = tid >> 5, lane = tid & 31;
    int bid = blockIdx.x;
    int ug = bid >> 2, bg = bid & 3;
    int u0 = ug * 16;
    int* donep = &g_done[bg * 32];

    int mt = wid & 3, ks = wid >> 2;
    int grp = lane >> 2, qid = lane & 3;

    uint32_t a[16][4];
    #pragma unroll
    for (int kk = 0; kk < 16; kk++)
        #pragma unroll
        for (int r = 0; r < 4; r++) {
            int m_loc = grp + (r & 1) * 8;
            int k = ks * 128 + kk * 8 + qid + (r >> 1) * 4;
            a[kk][r] = tf32r(Wh[(size_t)k * G_ + mt * 512 + u0 + m_loc]);
        }

    int u_l = tid & 15, b_l = tid >> 4;
    int u_cell = u0 + u_l, b_cell = bg * 16 + b_l;
    float creg = 0.0f;

    uint32_t bs_base = (uint32_t)__cvta_generic_to_shared(B_s);
    const uint32_t* Bu = (const uint32_t*)B_s;

    __syncthreads();

    for (int t = 0; t < T_; t++) {
        float xgv[4] = {0.f, 0.f, 0.f, 0.f};
        if (tid < 256) {
            size_t xoff = ((size_t)(b_cell * T_ + t)) * G_;
            #pragma unroll
            for (int g = 0; g < 4; g++)
                xgv[g] = g_xg[xoff + g * 512 + u_cell];
        }

        if (t > 0) {
            if (tid == 0) {
                int target = 32 * t, v;
                do {
                    asm volatile("ld.acquire.gpu.global.s32 %0, [%1];"
                                 : "=r"(v) : "l"(donep));
                } while (v < target);
            }
            __syncthreads();
            const float* src = g_hM[t & 1];
            #pragma unroll
            for (int q = 0; q < 4; q++) {
                int f = tid + q * 512;
                int u = f >> 2, j = f & 3;
                CP_ASYNC16(bs_base + (unsigned)((u * 24 + j * 4) * 4),
                           (const void*)&src[(size_t)u * 64 + bg * 16 + j * 4]);
            }
            CP_COMMIT();
            CP_WAIT(0);
        } else {
            #pragma unroll
            for (int i = 0; i < 6; i++)
                *(float4*)&B_s[(tid + i * 512) * 4] = make_float4(0.f, 0.f, 0.f, 0.f);
        }
        __syncthreads();

        float d0[4] = {0.f, 0.f, 0.f, 0.f};
        float d1[4] = {0.f, 0.f, 0.f, 0.f};
        #pragma unroll
        for (int kk = 0; kk < 16; kk++) {
            int kb = ks * 128 + kk * 8;
            uint32_t b0a = Bu[(kb + qid) * 24 + grp];
            uint32_t b1a = Bu[(kb + qid + 4) * 24 + grp];
            uint32_t b0b = Bu[(kb + qid) * 24 + 8 + grp];
            uint32_t b1b = Bu[(kb + qid + 4) * 24 + 8 + grp];
            MMA_TF32(d0, a[kk], b0a, b1a);
            MMA_TF32(d1, a[kk], b0b, b1b);
        }

        {
            float* rp = red + ks * 1088 + (mt * 16) * 17;
            int nc = qid * 2;
            rp[grp * 17 + nc]           = d0[0];
            rp[grp * 17 + nc + 1]       = d0[1];
            rp[(grp + 8) * 17 + nc]     = d0[2];
            rp[(grp + 8) * 17 + nc + 1] = d0[3];
            rp[grp * 17 + 8 + nc]           = d1[0];
            rp[grp * 17 + 8 + nc + 1]       = d1[1];
            rp[(grp + 8) * 17 + 8 + nc]     = d1[2];
            rp[(grp + 8) * 17 + 8 + nc + 1] = d1[3];
        }
        __syncthreads();

        if (tid < 256) {
            float sum[4];
            #pragma unroll
            for (int g = 0; g < 4; g++) {
                int cidx = (g * 16 + u_l) * 17 + b_l;
                sum[g] = red[cidx] + red[1088 + cidx] + red[2176 + cidx]
                       + red[3264 + cidx] + xgv[g];
            }
            float ig = sigf(sum[0]);
            float jg = tanhfast(sum[1]);
            float fg = sigf(sum[2] + 1.0f);                   // forget_bias = 1
            float og = sigf(sum[3]);
            creg = fg * creg + ig * jg;
            float hval = og * tanhfast(creg);
            hstage[u_l * 17 + b_l] = hval;
        }
        __syncthreads();

        if (tid < 256) {
            int u_loc = tid >> 4, b_loc = tid & 15;
            float v = hstage[u_loc * 17 + b_loc];
            ((uint32_t*)g_hM[(t + 1) & 1])[(size_t)(u0 + u_loc) * 64 + bg * 16 + b_loc] = tf32r(v);
        }
        __threadfence();
        __syncthreads();
        if (tid == 0)
            asm volatile("red.relaxed.gpu.global.add.s32 [%0], %1;"
                         :: "l"(donep), "r"(1) : "memory");

        if (tid < 256)
            g_hs[((size_t)(b_cell * T_ + t)) * H_ + u_cell] = hstage[u_l * 17 + b_l];
    }
}

// ============================================================
// Kernel C: out_loss via mma.sync tf32.
// Block = 32 bt-rows x 128 cols; 1024 blocks; 8 warps = 2 m-tiles x 4 n-quads.
// h staged once (tf32, pad 516); Wd streamed in 4 k-chunks (pad 132).
// ============================================================
#define OL_HS_PAD 516
#define OL_WS_PAD 132
#define OL_SMEM ((32 * OL_HS_PAD + 128 * OL_WS_PAD) * 4)   // 133632 B

__global__ void __launch_bounds__(256) out_loss(
    const float* __restrict__ Wd, const float* __restrict__ bd,
    const float* __restrict__ Y)
{
    extern __shared__ uint32_t sm[];
    uint32_t* Hs = sm;                       // [32 m][516] tf32
    uint32_t* Ws = sm + 32 * OL_HS_PAD;      // [128 k][132] tf32
    __shared__ float redsh[8];

    int tid = threadIdx.x;
    int m0 = blockIdx.x * 32;

    // stage full-K h rows as tf32 (coalesced over k)
    #pragma unroll
    for (int i = 0; i < 64; i++) {
        int idx = tid + i * 256;                 // 0..16383
        int m = idx >> 9, k = idx & 511;
        Hs[m * OL_HS_PAD + k] = tf32r(g_hs[(size_t)(m0 + m) * H_ + k]);
    }
    __syncthreads();

    int wid = tid >> 5, lane = tid & 31;
    int mt = wid & 1, nq = wid >> 1;             // m-tile 0..1, n-quad 0..3
    int grp = lane >> 2, qid = lane & 3;

    float d[4][4] = {};                          // [n-tile j][frag]
    #pragma unroll
    for (int kc = 0; kc < 4; kc++) {
        if (kc > 0) __syncthreads();             // protect Ws reuse
        // stage Wd chunk [128 k][128 n]
        #pragma unroll
        for (int i = 0; i < 64; i++) {
            int idx = tid + i * 256;             // 0..16383
            int k = idx >> 7, n = idx & 127;
            Ws[k * OL_WS_PAD + n] = tf32r(Wd[(size_t)(kc * 128 + k) * N_ + n]);
        }
        __syncthreads();

        #pragma unroll
        for (int kk = 0; kk < 16; kk++) {
            int kb = kk * 8;
            int ka = kc * 128 + kb;
            uint32_t a[4];
            a[0] = Hs[(mt * 16 + grp) * OL_HS_PAD + ka + qid];
            a[1] = Hs[(mt * 16 + grp + 8) * OL_HS_PAD + ka + qid];
            a[2] = Hs[(mt * 16 + grp) * OL_HS_PAD + ka + qid + 4];
            a[3] = Hs[(mt * 16 + grp + 8) * OL_HS_PAD + ka + qid + 4];
            #pragma unroll
            for (int j = 0; j < 4; j++) {
                int nt = nq * 4 + j;
                uint32_t b0 = Ws[(kb + qid) * OL_WS_PAD + nt * 8 + grp];
                uint32_t b1 = Ws[(kb + qid + 4) * OL_WS_PAD + nt * 8 + grp];
                MMA_TF32(d[j], a, b0, b1);
            }
        }
    }

    // epilogue: sigmoid + squared diff vs Y
    float lsum = 0.0f;
    #pragma unroll
    for (int j = 0; j < 4; j++) {
        int gn = (nq * 4 + j) * 8 + qid * 2;
        float2 bb = *(const float2*)&bd[gn];
        int r0 = m0 + mt * 16 + grp;
        float2 y0 = *(const float2*)&Y[(size_t)r0 * N_ + gn];
        float2 y1 = *(const float2*)&Y[(size_t)(r0 + 8) * N_ + gn];
        float l00 = sigf(d[j][0] + bb.x), l01 = sigf(d[j][1] + bb.y);
        float l10 = sigf(d[j][2] + bb.x), l11 = sigf(d[j][3] + bb.y);
        float e00 = y0.x - l00, e01 = y0.y - l01;
        float e10 = y1.x - l10, e11 = y1.y - l11;
        lsum += e00 * e00 + e01 * e01 + e10 * e10 + e11 * e11;
    }
    #pragma unroll
    for (int o = 16; o; o >>= 1) lsum += __shfl_xor_sync(0xFFFFFFFFu, lsum, o);
    if (lane == 0) redsh[wid] = lsum;
    __syncthreads();
    if (tid == 0) {
        float ssum = 0.0f;
        #pragma unroll
        for (int i = 0; i < 8; i++) ssum += redsh[i];
        g_lpart[blockIdx.x] = ssum;
    }
}

// ============================================================
__global__ void finalize(float* __restrict__ out)
{
    __shared__ float red[8];
    int tid = threadIdx.x;
    float sv = 0.0f;
    for (int i = tid; i < NLOSS; i += 256) sv += g_lpart[i];
    #pragma unroll
    for (int o = 16; o; o >>= 1) sv += __shfl_xor_sync(0xFFFFFFFFu, sv, o);
    if ((tid & 31) == 0) red[tid >> 5] = sv;
    __syncthreads();
    if (tid == 0) {
        float tt = 0.0f;
        #pragma unroll
        for (int i = 0; i < 8; i++) tt += red[i];
        out[0] = tt * (100.0f / ((float)B_ * (float)T_ * (float)N_));
    }
}

// ============================================================
extern "C" void kernel_launch(void* const* d_in, const int* in_sizes, int n_in,
                              void* d_out, int out_size)
{
    const float* X  = (const float*)d_in[0];
    const float* Y  = (const float*)d_in[1];
    const float* Wx = (const float*)d_in[2];
    const float* Wh = (const float*)d_in[3];
    const float* b  = (const float*)d_in[4];
    const float* Wd = (const float*)d_in[5];
    const float* bd = (const float*)d_in[6];
    (void)in_sizes; (void)n_in; (void)out_size;

    cudaFuncSetAttribute(xg_gemm, cudaFuncAttributeMaxDynamicSharedMemorySize, XG_SMEM);
    cudaFuncSetAttribute(lstm_scan, cudaFuncAttributeMaxDynamicSharedMemorySize, SMEM_SCAN);
    cudaFuncSetAttribute(out_loss, cudaFuncAttributeMaxDynamicSharedMemorySize, OL_SMEM);

    dim3 gA(G_ / 64, BT_ / 64);                 // 32 x 512
    xg_gemm<<<gA, 256, XG_SMEM>>>(X, Wx, b);    // also resets g_done
    lstm_scan<<<NBLK, 512, SMEM_SCAN>>>(Wh);
    out_loss<<<BT_ / 32, 256, OL_SMEM>>>(Wd, bd, Y);   // 1024 blocks
    finalize<<<1, 256>>>((float*)d_out);
}